// round 10
// baseline (speedup 1.0000x reference)
#include <cuda_runtime.h>

// TorchGrouper — round 10: round-9 memory pattern (best: 123.8us), but each
// block now handles HALF a g (32 k-rows, TPB=128, 8.6KB tile) -> 16
// independent blocks per SM (was 8) for better latency coverage.
// Block unit u: g = u>>1, khalf = u&1 (khalf fixed per block under stride).
// khalf0 additionally computes the mask (all 64 lookups) and writes gpf.
// Output: [C,G,K] features, [4,G,K] gpf, [G] mask (float 1/0).

#define ZDIM 40
#define YDIM 400
#define XDIM 400
#define KK 64
#define CC 64
#define TPB 128
#define NBLK 2368        // 148 SMs x 16 resident blocks
#define GSTRIDE (NBLK / 2)
#define TS 65            // tile row stride (floats)

__global__ __launch_bounds__(TPB, 16) void grouper_kernel(
    const int* __restrict__ vox,     // [N,Z,Y,X]
    const int* __restrict__ gpos,    // [G,4]
    const float* __restrict__ feat,  // [M,C]
    const int* __restrict__ off,     // [K,4]
    float* __restrict__ out,
    int G)
{
    __shared__ int      s_idx[2][32];
    __shared__ unsigned s_ball[2][2];
    __shared__ float    s_tile[32 * TS];

    const int t    = threadIdx.x;
    const int w    = t >> 5;
    const int lane = t & 31;
    const int khalf = blockIdx.x & 1;
    const size_t GK = (size_t)G * KK;
    float* out_gpf  = out + (size_t)CC * GK;
    float* out_mask = out + (size_t)(CC + 4) * GK;
    const float4* feat4 = reinterpret_cast<const float4*>(feat);

    // lookup duty: khalf0 -> k = t for t<64 (store t<32); khalf1 -> k = 32+t, t<32
    const bool lk_active = khalf ? (t < 32) : (t < 64);
    const int  lk_k      = khalf ? (32 + t) : t;
    int4 of = make_int4(0, 0, 0, 0);
    if (lk_active) of = reinterpret_cast<const int4*>(off)[lk_k];

    // gpf constants (khalf0 only): 2 entries per thread
    float gpf_v0 = 0.f, gpf_v1 = 0.f;
    if (khalf == 0) {
        gpf_v0 = (float)off[((2 * t) & 63) * 4 + ((2 * t) >> 6)];
        gpf_v1 = (float)off[((2 * t + 1) & 63) * 4 + ((2 * t + 1) >> 6)];
    }

    // drain mapping (conflict-free): lane -> (ql, dc)
    const int ql = lane & 7;             // k-quad within half (0..7)
    const int dc = lane >> 3;            // 0..3 c offset

    // ---- prologue: lookups for first g ----
    int g = blockIdx.x >> 1;
    if (lk_active) {
        const int4 gp = reinterpret_cast<const int4*>(gpos)[g];
        int z = min(max(gp.y + of.y, 0), ZDIM - 1);
        int y = min(max(gp.z + of.z, 0), YDIM - 1);
        int x = min(max(gp.w + of.w, 0), XDIM - 1);
        int idx = vox[((gp.x * ZDIM + z) * YDIM + y) * XDIM + x];
        if (t < 32) s_idx[0][t] = idx;
        unsigned m = __ballot_sync(0xffffffffu, idx >= 0);
        if (lane == 0 && w < 2) s_ball[0][w] = m;
    }
    __syncthreads();

    int p = 0;
    for (; g < G; g += GSTRIDE) {
        const int g_next = g + GSTRIDE;
        const bool has_next = (g_next < G);

        // ---- prefetch next g's lookups into registers ----
        int idxnext = -1;
        if (lk_active && has_next) {
            const int4 gp = reinterpret_cast<const int4*>(gpos)[g_next];
            int z = min(max(gp.y + of.y, 0), ZDIM - 1);
            int y = min(max(gp.z + of.z, 0), YDIM - 1);
            int x = min(max(gp.w + of.w, 0), XDIM - 1);
            idxnext = vox[((gp.x * ZDIM + z) * YDIM + y) * XDIM + x];
        }

        // ---- gather: 32 feature rows -> tile[k_local][c] ----
#pragma unroll
        for (int j = 0; j < 4; j++) {
            const int job = t + TPB * j;     // 0..511
            const int kl  = job >> 4;        // 0..31
            const int cq  = job & 15;
            const int idx = s_idx[p][kl];
            float4 v = make_float4(0.f, 0.f, 0.f, 0.f);
            if (idx >= 0) v = feat4[(size_t)idx * (CC / 4) + cq];
            float* dst = &s_tile[kl * TS + cq * 4];
            dst[0] = v.x; dst[1] = v.y; dst[2] = v.z; dst[3] = v.w;
        }
        __syncthreads();

        // ---- drain: transposed float4 streaming stores, CF LDS ----
#pragma unroll
        for (int j = 0; j < 4; j++) {
            const int task = w * 4 + j;              // 0..15
            const int c0   = task * 4;               // 0..60
            const int c    = c0 + dc;
            const int q    = ql;                     // 0..7 within half
            float4 v;
            v.x = s_tile[(q * 4 + 0) * TS + c];
            v.y = s_tile[(q * 4 + 1) * TS + c];
            v.z = s_tile[(q * 4 + 2) * TS + c];
            v.w = s_tile[(q * 4 + 3) * TS + c];
            __stcs(reinterpret_cast<float4*>(
                       out + (size_t)c * GK + (size_t)g * KK
                           + khalf * 32 + q * 4), v);
        }

        // ---- gpf + mask (khalf0 only) ----
        if (khalf == 0) {
            const int e0 = 2 * t, e1 = 2 * t + 1;
            __stcs(out_gpf + (size_t)(e0 >> 6) * GK + (size_t)g * KK + (e0 & 63), gpf_v0);
            __stcs(out_gpf + (size_t)(e1 >> 6) * GK + (size_t)g * KK + (e1 & 63), gpf_v1);
            if (t == 0)
                out_mask[g] = ((s_ball[p][0] | s_ball[p][1]) == 0u) ? 1.0f : 0.0f;
        }

        // ---- publish prefetched lookups into the other buffer ----
        if (lk_active && has_next) {
            if (t < 32) s_idx[1 - p][t] = idxnext;
            unsigned m = __ballot_sync(0xffffffffu, idxnext >= 0);
            if (lane == 0 && w < 2) s_ball[1 - p][w] = m;
        }
        __syncthreads();
        p ^= 1;
    }
}

extern "C" void kernel_launch(void* const* d_in, const int* in_sizes, int n_in,
                              void* d_out, int out_size) {
    const int*   vox  = (const int*)d_in[0];
    const int*   gpos = (const int*)d_in[1];
    const float* feat = (const float*)d_in[2];
    const int*   off  = (const int*)d_in[3];
    float* out = (float*)d_out;

    const int G = in_sizes[1] / 4;   // 30000
    grouper_kernel<<<NBLK, TPB>>>(vox, gpos, feat, off, out, G);
}